// round 5
// baseline (speedup 1.0000x reference)
#include <cuda_runtime.h>
#include <cuda_bf16.h>

#define NCTA 128
#define TPB  512
#define FPITERS 2
#define NIN0 14
#define NIN1 8
#define MAXSWEEP 8
#define FREESWEEPS 2     // sweeps rotated unconditionally (no threshold test)

// ---------------- device scratch (no allocation allowed) ----------------
__device__ __align__(16) float g_qf[4096];
__device__ __align__(16) float g_StS[4096];
__device__ __align__(16) float g_b[4096];
__device__ __align__(16) float g_x[4096];
__device__ __align__(16) float g_y[4096];
__device__ int g_cnt = 0;
__device__ int g_gen = 0;   // monotone across graph replays; g_cnt self-resets

// device-wide barrier: replay-safe (cnt self-resets; gen only increments)
__device__ __forceinline__ void gbar() {
    __threadfence();
    __syncthreads();
    if (threadIdx.x == 0) {
        int my = *(volatile int*)&g_gen;
        int old = atomicAdd(&g_cnt, 1);
        if (old == NCTA - 1) {
            g_cnt = 0;
            __threadfence();
            atomicAdd(&g_gen, 1);
        } else {
            while (*(volatile int*)&g_gen == my) { }
        }
    }
    __syncthreads();
    __threadfence();
}

struct SolveSm {
    float Ms[64*65];      // StS (apply); Ss staging (prep)
    float xs[4096];       // matvec x cache
    float zs[2][64];      // apply double buffer
};
struct FinalSm {
    float Gs[64*65];
    float Xs[64*65];
    float nrm[64];
    float sarr[64];
    float fsc[64];
    float thr_s;
};
union Smem { SolveSm s; FinalSm f; };

__global__ void __launch_bounds__(TPB, 1)
k_all(const float* __restrict__ inp, const float* __restrict__ L,
      const void* __restrict__ mask, const float* __restrict__ D,
      const float* __restrict__ thP, const float* __restrict__ vp,
      const float* __restrict__ netap, const float* __restrict__ lam1p,
      const float* __restrict__ lam2p, const float* __restrict__ rhop,
      const float* __restrict__ S, float* __restrict__ out) {
    __shared__ Smem sm;
    __shared__ int s_badU8, s_off1;
    int t = threadIdx.x;
    int cta = blockIdx.x;

    // ================= phase 0: prep (CTA0), StS (CTA1-4), D L2-warm (rest) ====
    if (cta == 0) {
        if (t == 0) { s_badU8 = 0; s_off1 = 0; }
        __syncthreads();
        const unsigned char* m8 = (const unsigned char*)mask;
        int b1 = 0, b2 = 0;
        for (int i = t; i < 4096; i += TPB) {
            unsigned v = m8[i];
            if (v > 1u) b1 = 1;
            if (v == 1u && (i & 3) != 0) b2 = 1;
        }
        if (b1) s_badU8 = 1;        // benign races
        if (b2) s_off1 = 1;
        __syncthreads();
        int mode = s_badU8 ? 1 : (s_off1 ? 0 : 2);   // 0=u8,1=f32,2=i32
        float rho = *rhop;
        for (int i = t; i < 4096; i += TPB) {
            bool on;
            if (mode == 0)      on = ((const unsigned char*)mask)[i] != 0;
            else if (mode == 1) on = ((const float*)mask)[i] != 0.0f;
            else                on = ((const int*)mask)[i] != 0;
            g_qf[i] = on ? 1.0f : 0.0f;
            g_b[i]  = rho * (L[i] - thP[i]) + (on ? inp[i] : 0.0f);
        }
    } else if (cta <= 4) {
        for (int i = t; i < 4096; i += TPB) { int h = i >> 6, a = i & 63; sm.s.Ms[h*65 + a] = S[i]; }
        __syncthreads();
        int base = (cta - 1) * 1024;
        #pragma unroll
        for (int k = 0; k < 2; k++) {
            int idx = base + t + k*TPB;
            int a = idx >> 6, b = idx & 63;
            float acc = 0.0f;
            #pragma unroll 16
            for (int h = 0; h < 64; h++) acc += sm.s.Ms[h*65 + a] * sm.s.Ms[h*65 + b];
            g_StS[idx] = acc;
        }
    } else {
        // warm D into L2: 123 CTAs stream 4096x4096 floats; sink into g_y
        // (g_y is fully overwritten by the first matvec, so this is inert).
        const float4* D4 = (const float4*)D;
        float4 acc4 = make_float4(0.f, 0.f, 0.f, 0.f);
        int total4 = 4096 * 1024;
        for (int i = (cta - 5) * TPB + t; i < total4; i += 123 * TPB) {
            float4 d = D4[i];
            acc4.x += d.x; acc4.y += d.y; acc4.z += d.z; acc4.w += d.w;
        }
        g_y[cta] = acc4.x + acc4.y + acc4.z + acc4.w;
    }
    gbar();   // 1

    float lam1 = *lam1p, lam2 = *lam2p, rho = *rhop;

    // apply CTAs stage StS into smem once; persists across apply phases
    if (cta < 64) {
        for (int i = t; i < 4096; i += TPB) { int a = i >> 6, c = i & 63; sm.s.Ms[a*65 + c] = g_StS[i]; }
        __syncthreads();
    }

    // ---------------- apply: x_h = B_h^{-1} r_h (Jacobi, 64 threads/CTA) -------
    auto apply = [&](int useY, int nin) {
        if (cta < 64 && t < 64) {
            int h = cta, u = t;
            float r = g_b[h*64 + u];
            if (useY) r -= lam1 * g_y[h*64 + u];
            float Muu  = sm.s.Ms[u*65 + u];
            float dinv = 1.0f / (rho + g_qf[h*64 + u] + lam2 * Muu);
            float z = useY ? g_x[h*64 + u] : r * dinv;
            int cur = 0;
            sm.s.zs[0][u] = z;
            asm volatile("bar.sync 1, 64;" ::: "memory");
            for (int it = 0; it < nin; it++) {
                float a0=0.f,a1=0.f,a2=0.f,a3=0.f;
                const float* Mr = &sm.s.Ms[u*65];
                const float* zc = sm.s.zs[cur];
                #pragma unroll 16
                for (int c = 0; c < 64; c += 4) {
                    a0 += Mr[c]   * zc[c];
                    a1 += Mr[c+1] * zc[c+1];
                    a2 += Mr[c+2] * zc[c+2];
                    a3 += Mr[c+3] * zc[c+3];
                }
                float acc = (a0+a1) + (a2+a3);
                z = (r - lam2 * (acc - Muu * z)) * dinv;
                if (it + 1 < nin) {
                    sm.s.zs[cur^1][u] = z;
                    asm volatile("bar.sync 1, 64;" ::: "memory");
                    cur ^= 1;
                }
            }
            g_x[h*64 + u] = z;
        }
    };

    // ---------------- matvec: y = D x (all 128 CTAs) ---------------------------
    auto matvec = [&]() {
        const float4* x4 = (const float4*)g_x;
        float4* xs4 = (float4*)sm.s.xs;
        for (int i = t; i < 1024; i += TPB) xs4[i] = x4[i];
        __syncthreads();
        int w = t >> 5, lane = t & 31;
        int row0 = cta * 32 + w * 2;
        #pragma unroll
        for (int rr = 0; rr < 2; rr++) {
            int row = row0 + rr;
            const float4* D4 = (const float4*)(D + (size_t)row * 4096);
            float acc = 0.0f;
            #pragma unroll
            for (int it = 0; it < 32; it++) {
                float4 d  = D4[lane + 32*it];
                float4 xv = xs4[lane + 32*it];
                acc += d.x*xv.x + d.y*xv.y + d.z*xv.z + d.w*xv.w;
            }
            #pragma unroll
            for (int off = 16; off > 0; off >>= 1)
                acc += __shfl_xor_sync(0xffffffffu, acc, off);
            if (lane == 0) g_y[row] = acc;
        }
        __syncthreads();   // xs reused next phase
    };

    apply(0, NIN0);
    gbar();   // 2
    for (int it = 0; it < FPITERS; it++) {
        matvec();
        gbar();           // 3, 5
        apply(1, NIN1);
        gbar();           // 4, 6
    }

    if (cta != 0) return;

    // ================= final: one-sided Jacobi SVD + SVT (CTA0 only) ==========
    float* Gs = sm.f.Gs;
    float* Xs = sm.f.Xs;
    float* nrm = sm.f.nrm;
    int w = t >> 5, lane = t & 31;

    for (int i = t; i < 4096; i += TPB) {
        int r = i >> 6, j = i & 63;
        float xv = g_x[i] + thP[i];
        Gs[j*65 + r] = xv;
        Xs[j*65 + r] = xv;
    }
    __syncthreads();
    if (t < 64) {
        float acc = 0.0f;
        #pragma unroll 16
        for (int r = 0; r < 64; r++) { float g = Gs[t*65 + r]; acc += g*g; }
        nrm[t] = acc;
    }
    __syncthreads();

    // warp w handles tournament pairs 2w, 2w+1; interleaved dual butterfly
    int k0 = w << 1, k1 = k0 + 1;
    for (int sweep = 0; sweep < MAXSWEEP; sweep++) {
        int did = 0;
        int free_rot = (sweep < FREESWEEPS);
        int p0, q0, p1, q1;
        if (k0 == 0) { p0 = 63; q0 = 0; }
        else { p0 = k0; q0 = 63 - k0; }
        p1 = k1; q1 = 63 - k1;
        for (int r = 0; r < 63; r++) {
            float a0 = Gs[p0*65 + lane], b0 = Gs[p0*65 + lane + 32];
            float c0 = Gs[q0*65 + lane], d0 = Gs[q0*65 + lane + 32];
            float a1 = Gs[p1*65 + lane], b1 = Gs[p1*65 + lane + 32];
            float c1 = Gs[q1*65 + lane], d1 = Gs[q1*65 + lane + 32];
            float dp0 = a0*c0 + b0*d0;
            float dp1 = a1*c1 + b1*d1;
            #pragma unroll
            for (int o = 16; o; o >>= 1) {   // two independent chains interleave
                dp0 += __shfl_xor_sync(0xffffffffu, dp0, o);
                dp1 += __shfl_xor_sync(0xffffffffu, dp1, o);
            }
            float npp0 = nrm[p0], nqq0 = nrm[q0];
            float npp1 = nrm[p1], nqq1 = nrm[q1];
            bool r0 = (dp0*dp0 > 1e-8f * npp0 * nqq0) ||
                      (free_rot && fabsf(dp0) > 1e-20f);
            bool r1 = (dp1*dp1 > 1e-8f * npp1 * nqq1) ||
                      (free_rot && fabsf(dp1) > 1e-20f);
            if (r0) {
                float zeta = __fdividef(nqq0 - npp0, 2.0f * dp0);
                float tt = copysignf(__fdividef(1.0f, fabsf(zeta) + __fsqrt_rn(1.0f + zeta*zeta)), zeta);
                float c = __frsqrt_rn(1.0f + tt*tt), s = tt * c;
                Gs[p0*65 + lane]      = c*a0 - s*c0;
                Gs[q0*65 + lane]      = s*a0 + c*c0;
                Gs[p0*65 + lane + 32] = c*b0 - s*d0;
                Gs[q0*65 + lane + 32] = s*b0 + c*d0;
                if (lane == 0) { nrm[p0] = npp0 - tt*dp0; nrm[q0] = nqq0 + tt*dp0; }
                did = 1;
            }
            if (r1) {
                float zeta = __fdividef(nqq1 - npp1, 2.0f * dp1);
                float tt = copysignf(__fdividef(1.0f, fabsf(zeta) + __fsqrt_rn(1.0f + zeta*zeta)), zeta);
                float c = __frsqrt_rn(1.0f + tt*tt), s = tt * c;
                Gs[p1*65 + lane]      = c*a1 - s*c1;
                Gs[q1*65 + lane]      = s*a1 + c*c1;
                Gs[p1*65 + lane + 32] = c*b1 - s*d1;
                Gs[q1*65 + lane + 32] = s*b1 + c*d1;
                if (lane == 0) { nrm[p1] = npp1 - tt*dp1; nrm[q1] = nqq1 + tt*dp1; }
                did = 1;
            }
            __syncthreads();
            if (k0 == 0) { q0 = (q0 + 1 == 63) ? 0 : q0 + 1; }
            else { p0 = (p0 + 1 == 63) ? 0 : p0 + 1; q0 = (q0 + 1 == 63) ? 0 : q0 + 1; }
            p1 = (p1 + 1 == 63) ? 0 : p1 + 1;
            q1 = (q1 + 1 == 63) ? 0 : q1 + 1;
        }
        if (sweep >= FREESWEEPS && !__syncthreads_or(did)) break;
    }

    // singular values + threshold
    if (t < 64) {
        float acc = 0.0f;
        #pragma unroll 16
        for (int r = 0; r < 64; r++) { float g = Gs[t*65 + r]; acc += g*g; }
        sm.f.sarr[t] = sqrtf(acc);
    }
    __syncthreads();
    if (t == 0) {
        float m = 0.0f;
        for (int j = 0; j < 64; j++) m = fmaxf(m, sm.f.sarr[j]);
        float vv = *vp;
        float tau = 0.4f / (1.0f + expf(-vv));
        sm.f.thr_s = tau * m;
    }
    __syncthreads();
    if (t < 64) {
        float s = sm.f.sarr[t];
        float st = s - sm.f.thr_s;
        sm.f.fsc[t] = (st > 0.0f) ? st / (s*s*s) : 0.0f;
    }
    __syncthreads();

    // W[j][c] = fsc[j] * sum_r G[r,j] X[r,c]
    float wreg[8];
    #pragma unroll
    for (int k = 0; k < 8; k++) {
        int idx = t + k*TPB;
        int jj = idx >> 6, c = idx & 63;
        float acc = 0.0f;
        #pragma unroll 16
        for (int r = 0; r < 64; r++) acc += Gs[jj*65 + r] * Xs[c*65 + r];
        wreg[k] = acc * sm.f.fsc[jj];
    }
    __syncthreads();
    #pragma unroll
    for (int k = 0; k < 8; k++) {
        int idx = t + k*TPB;
        int jj = idx >> 6, c = idx & 63;
        Xs[c*65 + jj] = wreg[k];   // W, transposed layout
    }
    __syncthreads();

    // Ltmp = G W ; Ptmp = thP + neta*(x - Ltmp)
    float neta = *netap;
    #pragma unroll
    for (int k = 0; k < 8; k++) {
        int i = t + k*TPB;
        int r = i >> 6, c = i & 63;
        float acc = 0.0f;
        #pragma unroll 16
        for (int j = 0; j < 64; j++) acc += Gs[j*65 + r] * Xs[c*65 + j];
        out[i]        = acc;
        out[4096 + i] = thP[i] + neta * (g_x[i] - acc);
    }
}

// ---------------- launch ----------------
extern "C" void kernel_launch(void* const* d_in, const int* in_sizes, int n_in,
                              void* d_out, int out_size) {
    const float* inp  = (const float*)d_in[0];
    const float* L    = (const float*)d_in[1];
    const void*  mask = d_in[2];
    const float* D    = (const float*)d_in[3];
    const float* thP  = (const float*)d_in[4];
    const float* v    = (const float*)d_in[5];
    const float* neta = (const float*)d_in[6];
    const float* lam1 = (const float*)d_in[7];
    const float* lam2 = (const float*)d_in[8];
    const float* rho  = (const float*)d_in[9];
    const float* S    = (const float*)d_in[10];
    float* out = (float*)d_out;

    k_all<<<NCTA, TPB>>>(inp, L, mask, D, thP, v, neta, lam1, lam2, rho, S, out);
}

// round 6
// speedup vs baseline: 1.4765x; 1.4765x over previous
#include <cuda_runtime.h>
#include <cuda_bf16.h>

#define NCTA 128
#define TPB  512
#define FPITERS 2
#define NIN0 14
#define NIN1 8
#define MAXSWEEP 7

// ---------------- device scratch (no allocation allowed) ----------------
__device__ __align__(16) float g_qf[4096];
__device__ __align__(16) float g_StS[4096];
__device__ __align__(16) float g_b[4096];
__device__ __align__(16) float g_x[4096];
__device__ __align__(16) float g_y[4096];
__device__ int g_cnt = 0;
__device__ int g_gen = 0;   // monotone across graph replays; g_cnt self-resets

// device-wide barrier: replay-safe (cnt self-resets; gen only increments)
__device__ __forceinline__ void gbar() {
    __threadfence();
    __syncthreads();
    if (threadIdx.x == 0) {
        int my = *(volatile int*)&g_gen;
        int old = atomicAdd(&g_cnt, 1);
        if (old == NCTA - 1) {
            g_cnt = 0;
            __threadfence();
            atomicAdd(&g_gen, 1);
        } else {
            while (*(volatile int*)&g_gen == my) { }
        }
    }
    __syncthreads();
    __threadfence();
}

struct SolveSm {
    float Ms[64*65];      // StS (apply); Ss staging (prep)
    float xs[4096];       // matvec x cache
    float zs[2][64];      // apply double buffer
};
struct FinalSm {
    float Gf[64*68];      // column j at Gf[j*68 + r]; float4-aligned (68*4 % 16 == 0)
    float Xs[64*65];      // pristine X (later reused for W)
    float nrm[64];
    float sarr[64];
    float fsc[64];
    float thr_s;
};
union __align__(16) Smem { SolveSm s; FinalSm f; };

__global__ void __launch_bounds__(TPB, 1)
k_all(const float* __restrict__ inp, const float* __restrict__ L,
      const void* __restrict__ mask, const float* __restrict__ D,
      const float* __restrict__ thP, const float* __restrict__ vp,
      const float* __restrict__ netap, const float* __restrict__ lam1p,
      const float* __restrict__ lam2p, const float* __restrict__ rhop,
      const float* __restrict__ S, float* __restrict__ out) {
    __shared__ Smem sm;
    __shared__ int s_badU8, s_off1;
    int t = threadIdx.x;
    int cta = blockIdx.x;

    // ================= phase 0: prep (CTA0), StS (CTA1-4), D L2-warm (rest) ====
    if (cta == 0) {
        if (t == 0) { s_badU8 = 0; s_off1 = 0; }
        __syncthreads();
        const unsigned char* m8 = (const unsigned char*)mask;
        int b1 = 0, b2 = 0;
        for (int i = t; i < 4096; i += TPB) {
            unsigned v = m8[i];
            if (v > 1u) b1 = 1;
            if (v == 1u && (i & 3) != 0) b2 = 1;
        }
        if (b1) s_badU8 = 1;        // benign races
        if (b2) s_off1 = 1;
        __syncthreads();
        int mode = s_badU8 ? 1 : (s_off1 ? 0 : 2);   // 0=u8,1=f32,2=i32
        float rho = *rhop;
        for (int i = t; i < 4096; i += TPB) {
            bool on;
            if (mode == 0)      on = ((const unsigned char*)mask)[i] != 0;
            else if (mode == 1) on = ((const float*)mask)[i] != 0.0f;
            else                on = ((const int*)mask)[i] != 0;
            g_qf[i] = on ? 1.0f : 0.0f;
            g_b[i]  = rho * (L[i] - thP[i]) + (on ? inp[i] : 0.0f);
        }
    } else if (cta <= 4) {
        for (int i = t; i < 4096; i += TPB) { int h = i >> 6, a = i & 63; sm.s.Ms[h*65 + a] = S[i]; }
        __syncthreads();
        int base = (cta - 1) * 1024;
        #pragma unroll
        for (int k = 0; k < 2; k++) {
            int idx = base + t + k*TPB;
            int a = idx >> 6, b = idx & 63;
            float acc = 0.0f;
            #pragma unroll 16
            for (int h = 0; h < 64; h++) acc += sm.s.Ms[h*65 + a] * sm.s.Ms[h*65 + b];
            g_StS[idx] = acc;
        }
    } else {
        // warm D into L2 (sink into g_y; fully overwritten by first matvec)
        const float4* D4 = (const float4*)D;
        float4 acc4 = make_float4(0.f, 0.f, 0.f, 0.f);
        int total4 = 4096 * 1024;
        for (int i = (cta - 5) * TPB + t; i < total4; i += 123 * TPB) {
            float4 d = D4[i];
            acc4.x += d.x; acc4.y += d.y; acc4.z += d.z; acc4.w += d.w;
        }
        g_y[cta] = acc4.x + acc4.y + acc4.z + acc4.w;
    }
    gbar();   // 1

    float lam1 = *lam1p, lam2 = *lam2p, rho = *rhop;

    if (cta < 64) {
        for (int i = t; i < 4096; i += TPB) { int a = i >> 6, c = i & 63; sm.s.Ms[a*65 + c] = g_StS[i]; }
        __syncthreads();
    }

    // ---------------- apply: x_h = B_h^{-1} r_h (Jacobi, 64 threads/CTA) -------
    auto apply = [&](int useY, int nin) {
        if (cta < 64 && t < 64) {
            int h = cta, u = t;
            float r = g_b[h*64 + u];
            if (useY) r -= lam1 * g_y[h*64 + u];
            float Muu  = sm.s.Ms[u*65 + u];
            float dinv = 1.0f / (rho + g_qf[h*64 + u] + lam2 * Muu);
            float z = useY ? g_x[h*64 + u] : r * dinv;
            int cur = 0;
            sm.s.zs[0][u] = z;
            asm volatile("bar.sync 1, 64;" ::: "memory");
            for (int it = 0; it < nin; it++) {
                float a0=0.f,a1=0.f,a2=0.f,a3=0.f;
                const float* Mr = &sm.s.Ms[u*65];
                const float* zc = sm.s.zs[cur];
                #pragma unroll 16
                for (int c = 0; c < 64; c += 4) {
                    a0 += Mr[c]   * zc[c];
                    a1 += Mr[c+1] * zc[c+1];
                    a2 += Mr[c+2] * zc[c+2];
                    a3 += Mr[c+3] * zc[c+3];
                }
                float acc = (a0+a1) + (a2+a3);
                z = (r - lam2 * (acc - Muu * z)) * dinv;
                if (it + 1 < nin) {
                    sm.s.zs[cur^1][u] = z;
                    asm volatile("bar.sync 1, 64;" ::: "memory");
                    cur ^= 1;
                }
            }
            g_x[h*64 + u] = z;
        }
    };

    // ---------------- matvec: y = D x (all 128 CTAs) ---------------------------
    auto matvec = [&]() {
        const float4* x4 = (const float4*)g_x;
        float4* xs4 = (float4*)sm.s.xs;
        for (int i = t; i < 1024; i += TPB) xs4[i] = x4[i];
        __syncthreads();
        int w = t >> 5, lane = t & 31;
        int row0 = cta * 32 + w * 2;
        #pragma unroll
        for (int rr = 0; rr < 2; rr++) {
            int row = row0 + rr;
            const float4* D4 = (const float4*)(D + (size_t)row * 4096);
            float acc = 0.0f;
            #pragma unroll
            for (int it = 0; it < 32; it++) {
                float4 d  = D4[lane + 32*it];
                float4 xv = xs4[lane + 32*it];
                acc += d.x*xv.x + d.y*xv.y + d.z*xv.z + d.w*xv.w;
            }
            #pragma unroll
            for (int off = 16; off > 0; off >>= 1)
                acc += __shfl_xor_sync(0xffffffffu, acc, off);
            if (lane == 0) g_y[row] = acc;
        }
        __syncthreads();
    };

    apply(0, NIN0);
    gbar();   // 2
    for (int it = 0; it < FPITERS; it++) {
        matvec();
        gbar();
        apply(1, NIN1);
        gbar();
    }

    if (cta != 0) return;

    // ================= final: one-sided Jacobi SVD + SVT (CTA0 only) ==========
    float* Gf = sm.f.Gf;
    float4* Gc = (float4*)sm.f.Gf;      // column j: Gc[j*17 + k] = rows 4k..4k+3
    float* Xs = sm.f.Xs;
    float* nrm = sm.f.nrm;
    int lane = t & 31, w = t >> 5;

    for (int i = t; i < 4096; i += TPB) {
        int r = i >> 6, j = i & 63;
        float xv = g_x[i] + thP[i];
        Gf[j*68 + r] = xv;
        Xs[j*65 + r] = xv;
    }
    __syncthreads();
    if (t < 64) {
        float acc = 0.0f;
        #pragma unroll 16
        for (int r = 0; r < 64; r++) { float g = Gf[t*68 + r]; acc += g*g; }
        nrm[t] = acc;
    }
    __syncthreads();

    // 16 warps x 2 pairs (16-lane groups). Pair id k = 2w + (lane>=16).
    int grp = lane >> 4;
    int kk  = lane & 15;                 // float4 row block within column
    int k   = (w << 1) | grp;
    for (int sweep = 0; sweep < MAXSWEEP; sweep++) {
        int did = 0;
        int p, q;
        if (k == 0) { p = 63; q = 0; }
        else { p = k; q = 63 - k; }
        for (int r = 0; r < 63; r++) {
            float4 gp = Gc[p*17 + kk];
            float4 gq = Gc[q*17 + kk];
            float dp = gp.x*gq.x + gp.y*gq.y + gp.z*gq.z + gp.w*gq.w;
            #pragma unroll
            for (int o = 8; o; o >>= 1) dp += __shfl_xor_sync(0xffffffffu, dp, o);
            float npp = nrm[p], nqq = nrm[q];
            if (dp*dp > 1e-14f * npp * nqq) {
                float zeta = __fdividef(nqq - npp, 2.0f * dp);
                float tt = copysignf(__fdividef(1.0f, fabsf(zeta) + __fsqrt_rn(1.0f + zeta*zeta)), zeta);
                float c = __frsqrt_rn(1.0f + tt*tt), s = tt * c;
                float4 np4, nq4;
                np4.x = c*gp.x - s*gq.x;  nq4.x = s*gp.x + c*gq.x;
                np4.y = c*gp.y - s*gq.y;  nq4.y = s*gp.y + c*gq.y;
                np4.z = c*gp.z - s*gq.z;  nq4.z = s*gp.z + c*gq.z;
                np4.w = c*gp.w - s*gq.w;  nq4.w = s*gp.w + c*gq.w;
                Gc[p*17 + kk] = np4;
                Gc[q*17 + kk] = nq4;
                if (kk == 0) { nrm[p] = npp - tt*dp; nrm[q] = nqq + tt*dp; }
                did = 1;
            }
            __syncthreads();
            if (k == 0) { q = (q + 1 == 63) ? 0 : q + 1; }
            else { p = (p + 1 == 63) ? 0 : p + 1; q = (q + 1 == 63) ? 0 : q + 1; }
        }
        if (sweep >= 3 && !__syncthreads_or(did)) break;
    }

    // singular values + threshold
    if (t < 64) {
        float acc = 0.0f;
        #pragma unroll 16
        for (int r = 0; r < 64; r++) { float g = Gf[t*68 + r]; acc += g*g; }
        sm.f.sarr[t] = sqrtf(acc);
    }
    __syncthreads();
    if (t == 0) {
        float m = 0.0f;
        for (int j = 0; j < 64; j++) m = fmaxf(m, sm.f.sarr[j]);
        float vv = *vp;
        float tau = 0.4f / (1.0f + expf(-vv));
        sm.f.thr_s = tau * m;
    }
    __syncthreads();
    if (t < 64) {
        float s = sm.f.sarr[t];
        float st = s - sm.f.thr_s;
        sm.f.fsc[t] = (st > 0.0f) ? st / (s*s*s) : 0.0f;
    }
    __syncthreads();

    // W[j][c] = fsc[j] * sum_r G[r,j] X[r,c]   (G read via uniform broadcast)
    float wreg[8];
    #pragma unroll
    for (int kq = 0; kq < 8; kq++) {
        int idx = t + kq*TPB;
        int jj = idx >> 6, c = idx & 63;
        float acc = 0.0f;
        #pragma unroll 16
        for (int r = 0; r < 64; r++) acc += Gf[jj*68 + r] * Xs[c*65 + r];
        wreg[kq] = acc * sm.f.fsc[jj];
    }
    __syncthreads();
    #pragma unroll
    for (int kq = 0; kq < 8; kq++) {
        int idx = t + kq*TPB;
        int jj = idx >> 6, c = idx & 63;
        Xs[c*65 + jj] = wreg[kq];   // W, transposed layout
    }
    __syncthreads();

    // Ltmp = G W ; Ptmp = thP + neta*(x - Ltmp)
    float neta = *netap;
    #pragma unroll
    for (int kq = 0; kq < 8; kq++) {
        int i = t + kq*TPB;
        int r = i >> 6, c = i & 63;
        float acc = 0.0f;
        #pragma unroll 16
        for (int j = 0; j < 64; j++) acc += Gf[j*68 + r] * Xs[c*65 + j];
        out[i]        = acc;
        out[4096 + i] = thP[i] + neta * (g_x[i] - acc);
    }
}

// ---------------- launch ----------------
extern "C" void kernel_launch(void* const* d_in, const int* in_sizes, int n_in,
                              void* d_out, int out_size) {
    const float* inp  = (const float*)d_in[0];
    const float* L    = (const float*)d_in[1];
    const void*  mask = d_in[2];
    const float* D    = (const float*)d_in[3];
    const float* thP  = (const float*)d_in[4];
    const float* v    = (const float*)d_in[5];
    const float* neta = (const float*)d_in[6];
    const float* lam1 = (const float*)d_in[7];
    const float* lam2 = (const float*)d_in[8];
    const float* rho  = (const float*)d_in[9];
    const float* S    = (const float*)d_in[10];
    float* out = (float*)d_out;

    k_all<<<NCTA, TPB>>>(inp, L, mask, D, thP, v, neta, lam1, lam2, rho, S, out);
}